// round 13
// baseline (speedup 1.0000x reference)
#include <cuda_runtime.h>
#include <cstdint>

#define BB   4
#define NHH  8
#define NN   1024
#define MM   21
#define CC   32
#define HD   4
#define DD   84
#define NROWS (BB*NN*MM)

// ---------------- device scratch ----------------
__device__ float g_q[BB*NHH*NN*DD];
__device__ float g_k[BB*NHH*NN*DD];
__device__ float g_v[BB*NHH*NN*DD];      // row-major (bh, n, d84)
__device__ float g_x2[BB*NHH*NN];
__device__ float g_pool[BB*NHH];
__device__ float g_xw[NHH*NN];
__device__ float g_xp[NHH*NN];
__device__ float g_tb[NHH*63*63];
__device__ float g_rowmax[NHH*NN];
__device__ float g_ctx[NROWS*CC];

__device__ __forceinline__ float tf32_hi(float f) {
    return __uint_as_float(__float_as_uint(f) & 0xFFFFE000u);
}
__device__ __forceinline__ unsigned tf32_rnd(float f) {
    return (__float_as_uint(f) + 0x1000u) & 0xFFFFE000u;
}

#define MMA_TF32(C, A0, A1, A2, A3, B0, B1) \
    asm volatile( \
        "mma.sync.aligned.m16n8k8.row.col.f32.tf32.tf32.f32 " \
        "{%0,%1,%2,%3}, {%4,%5,%6,%7}, {%8,%9}, {%0,%1,%2,%3};\n" \
        : "+f"((C)[0]), "+f"((C)[1]), "+f"((C)[2]), "+f"((C)[3]) \
        : "r"(A0), "r"(A1), "r"(A2), "r"(A3), "r"(B0), "r"(B1))

// ---------------- kernel A: qkv projection (coalesced writes) + fused x2 ----
#define QKV_OUT 0
#define QKV_XS  8400
#define QKV_WS  (QKV_XS + 84*33)
#define QKV_WSQ (QKV_WS + 3072)
#define QKV_SMEMF (QKV_WSQ + 84)

__global__ void __launch_bounds__(256) qkv2_kernel(const float* __restrict__ x,
                                                   const float* __restrict__ Wq,
                                                   const float* __restrict__ bq,
                                                   const float* __restrict__ Wsq,
                                                   const float* __restrict__ bsq) {
    extern __shared__ float sm[];
    float* out = sm + QKV_OUT;
    float* xs  = sm + QKV_XS;
    float* Ws  = sm + QKV_WS;
    float* wsq = sm + QKV_WSQ;
    int t = threadIdx.x;
    int blk = blockIdx.x;                       // 0..1023, 4 groups each
    long xbase = (long)blk * 84 * 32;

    for (int i = t; i < 84*32; i += 256) xs[(i >> 5)*33 + (i & 31)] = x[xbase + i];
    for (int i = t; i < 3072; i += 256) Ws[i] = Wq[i];
    if (t < 84) wsq[t] = Wsq[t];
    __syncthreads();

    if (t < 252) {
        int ry = t % 84, cg = t / 84;           // cg = which (0:q,1:k,2:v)
        float acc[32];
#pragma unroll
        for (int j = 0; j < 32; j++) acc[j] = bq[cg*32 + j];
        for (int kk = 0; kk < 32; kk++) {
            float xv = xs[ry*33 + kk];
#pragma unroll
            for (int j = 0; j < 32; j++) acc[j] += xv * Ws[kk*96 + cg*32 + j];
        }
#pragma unroll
        for (int j = 0; j < 32; j++) out[ry*100 + cg*32 + j] = acc[j];
    }

    // fused x2: one value per (group, head)
    if (t < 32) {
        int g = t >> 3, h = t & 7;
        float acc = bsq[0];
        for (int m = 0; m < 21; m++)
#pragma unroll
            for (int d = 0; d < 4; d++)
                acc += xs[(g*21 + m)*33 + h*4 + d] * wsq[m*4 + d];
        int b_ = blk*4 + g;
        g_x2[((b_ >> 10)*8 + h)*1024 + (b_ & 1023)] = acc;
    }
    __syncthreads();

    // coalesced write-out: 96 rows (4 groups x 8 heads x 3 tensors) of 84 floats
    int w = t >> 5, lane = t & 31;
#pragma unroll
    for (int it = 0; it < 12; it++) {
        int tk = w*12 + it;
        int g = tk / 24, rem = tk % 24, which = rem >> 3, h = rem & 7;
        int b_ = blk*4 + g;
        int bh = (b_ >> 10)*8 + h, n = b_ & 1023;
        float* dst = (which == 0 ? g_q : which == 1 ? g_k : g_v)
                     + ((long)bh*1024 + n)*84;
        for (int d84 = lane; d84 < 84; d84 += 32) {
            float s = out[(g*21 + (d84 >> 2))*100 + which*32 + h*4 + (d84 & 3)];
            dst[d84] = (which == 0) ? s * 0.03125f : s;
        }
    }
}

// ---------------- LSPE small kernels ----------------
__global__ void pool_kernel() {
    int bh = blockIdx.x, t = threadIdx.x;
    const float* p = g_x2 + bh*NN;
    float s = 0.f, mx = -1e30f;
    for (int i = t; i < NN; i += 256) { float v = p[i]; s += v; mx = fmaxf(mx, v); }
    __shared__ float ss[256], sm_[256];
    ss[t] = s; sm_[t] = mx;
    __syncthreads();
    for (int o = 128; o > 0; o >>= 1) {
        if (t < o) { ss[t] += ss[t+o]; sm_[t] = fmaxf(sm_[t], sm_[t+o]); }
        __syncthreads();
    }
    if (t == 0) g_pool[bh] = ss[0]*(1.f/1024.f) + sm_[0];
}

// conv: one block per input channel (group); 4 batch planes staged with zero halo
__global__ void __launch_bounds__(1024) conv_kernel(const float* __restrict__ Wdw,
                                                    const float* __restrict__ bdw) {
    int ic = blockIdx.x, t = threadIdx.x;
    __shared__ float sp[4*34*34];
    for (int i = t; i < 4*34*34; i += 1024) sp[i] = 0.f;
    __syncthreads();
    for (int i = t; i < 4096; i += 1024) {
        int b = i >> 10, pos = i & 1023;
        int y = pos >> 5, x = pos & 31;
        sp[b*1156 + (y+1)*34 + (x+1)] = g_x2[(b*NHH + ic)*NN + pos];
    }
    int o0 = 2*ic, o1 = 2*ic + 1;
    float w0[9], w1[9];
#pragma unroll
    for (int j = 0; j < 9; j++) { w0[j] = Wdw[o0*9 + j]; w1[j] = Wdw[o1*9 + j]; }
    float bd0 = bdw[o0], bd1 = bdw[o1];
    __syncthreads();

    int y = t >> 5, x = t & 31;
    float acc0 = 0.f, acc1 = 0.f;
#pragma unroll
    for (int b = 0; b < 4; b++) {
        const float* base = sp + b*1156 + y*34 + x;
        float pm0 = g_pool[b*NHH + (o0 & 7)];
        float pm1 = g_pool[b*NHH + (o1 & 7)];
        float c0 = bd0 + pm0, c1 = bd1 + pm1;
#pragma unroll
        for (int ky = 0; ky < 3; ky++)
#pragma unroll
            for (int kx = 0; kx < 3; kx++) {
                float s = base[ky*34 + kx];
                c0 += s * w0[ky*3 + kx];
                c1 += s * w1[ky*3 + kx];
            }
        acc0 += c0; acc1 += c1;
    }
    acc0 *= 0.25f; acc1 *= 0.25f;
    if (o0 < 8) { g_xw[o0*NN + t] = acc0; g_xw[o1*NN + t] = acc1; }
    else        { g_xp[(o0-8)*NN + t] = acc0; g_xp[(o1-8)*NN + t] = acc1; }
}

// table: grid (63, 8), 512 threads; 8 threads per output, padded pitch 33
__global__ void __launch_bounds__(512) table_kernel() {
    int p = blockIdx.x, h = blockIdx.y, t = threadIdx.x;
    __shared__ float xw[32*33], xp[32*33];
    for (int i = t; i < 1024; i += 512) {
        int r = i >> 5, c = i & 31;
        xw[r*33 + c] = g_xw[h*NN + i];
        xp[r*33 + c] = g_xp[h*NN + i];
    }
    __syncthreads();
    int q = t >> 3, part = t & 7;            // q 0..63 (63 unused)
    int alo = max(0, p-31), ahi = min(31, p);
    int blo = max(0, q-31), bhi = min(31, q);
    float acc0 = 0.f, acc1 = 0.f;
    for (int a = alo + part; a <= ahi; a += 8) {
        const float* xwr = xw + a*33;
        const float* xpr = xp + (p-a)*33;
        for (int b2 = blo; b2 + 1 <= bhi; b2 += 2) {
            acc0 += xwr[b2]     * xpr[q - b2];
            acc1 += xwr[b2 + 1] * xpr[q - b2 - 1];
        }
        if (((bhi - blo) & 1) == 0) acc0 += xwr[bhi] * xpr[q - bhi];
    }
    float acc = acc0 + acc1;
    acc += __shfl_xor_sync(0xffffffffu, acc, 1);
    acc += __shfl_xor_sync(0xffffffffu, acc, 2);
    acc += __shfl_xor_sync(0xffffffffu, acc, 4);
    if (part == 0 && q < 63) g_tb[h*3969 + p*63 + q] = acc;
}

// rowmax: separable 32x32 window max (col-max pass, then row-max pass)
__global__ void __launch_bounds__(256) rowmax_kernel() {
    int h = blockIdx.x, t = threadIdx.x;
    __shared__ float tb[3969];
    __shared__ float cm[32*63];
    for (int i = t; i < 3969; i += 256) tb[i] = g_tb[h*3969 + i];
    __syncthreads();
    for (int i = t; i < 32*63; i += 256) {
        int i1 = i / 63, j = i % 63;
        float m = tb[i1*63 + j];
#pragma unroll 4
        for (int a = 1; a < 32; a++) m = fmaxf(m, tb[(i1+a)*63 + j]);
        cm[i] = m;
    }
    __syncthreads();
    for (int n1 = t; n1 < 1024; n1 += 256) {
        int i1 = n1 >> 5, j1 = n1 & 31;
        float m = cm[i1*63 + j1];
#pragma unroll 4
        for (int b = 1; b < 32; b++) m = fmaxf(m, cm[i1*63 + j1 + b]);
        g_rowmax[h*NN + n1] = m;
    }
}

// ---------------- HMMA tf32 flash attention ----------------
// SMEM: Kp 11*64*4 float2 = 22528 | V4 88*36 float4 = 50688 | TBs 2205 f = 8820
#define KP_OFF 0
#define V4_OFF 22528
#define TB_OFF 73216
#define SMEM_BYTES 82048

__global__ void __launch_bounds__(256, 2) flash_mma() {
    extern __shared__ char smem[];
    float2* Kp  = (float2*)(smem + KP_OFF);
    float*  KpW = (float*)(smem + KP_OFF);
    float4* V4  = (float4*)(smem + V4_OFF);
    float*  V4W = (float*)(smem + V4_OFF);
    float*  TBs = (float*)(smem + TB_OFF);

    int t = threadIdx.x;
    int w = t >> 5, lane = t & 31;
    int g = lane >> 2, tid = lane & 3;
    int qt = blockIdx.x, bh = blockIdx.y;
    int h = bh & 7, b = bh >> 3;
    int q0 = qt * 128;

    const float* qptr = g_q + (long)bh*NN*DD;
    const float* kptr = g_k + (long)bh*NN*DD;
    const float* vptr = g_v + (long)bh*NN*DD;

    // bias table slice rows [qt*4 .. qt*4+34]
    int i1base = qt * 4;
    for (int i = t; i < 2205; i += 256) TBs[i] = g_tb[h*3969 + i1base*63 + i];
    // zero pad slots never written by staging:
    //   Kp ks=10 .y words (d = 84..87)
    if (t < 256) KpW[(10*256 + t)*2 + 1] = 0.f;
    //   V4 rows d = 84..87
    for (int i = t; i < 4*36; i += 256)
        V4[84*36 + i] = make_float4(0.f, 0.f, 0.f, 0.f);

    // Q fragments: rows r0 = q0+w*16+g, r1 = r0+8; 11 ksteps
    unsigned qa[11][4];
    int r0 = q0 + w*16 + g, r1 = r0 + 8;
#pragma unroll
    for (int ks = 0; ks < 11; ks++) {
        int d0 = ks*8 + tid;
        qa[ks][0] = __float_as_uint(qptr[(long)r0*84 + d0]);
        qa[ks][1] = __float_as_uint(qptr[(long)r1*84 + d0]);
        qa[ks][2] = (d0+4 < 84) ? __float_as_uint(qptr[(long)r0*84 + d0+4]) : 0u;
        qa[ks][3] = (d0+4 < 84) ? __float_as_uint(qptr[(long)r1*84 + d0+4]) : 0u;
    }

    float mr0 = g_rowmax[h*NN + r0] + 1.0f;
    float mr1 = g_rowmax[h*NN + r1] + 1.0f;
    int base0 = ((r0 >> 5) - i1base + 31)*63 + (r0 & 31) + 31;
    int base1 = ((r1 >> 5) - i1base + 31)*63 + (r1 & 31) + 31;
    float lacc0 = 0.f, lacc1 = 0.f;

    float oc[11][4];
#pragma unroll
    for (int db = 0; db < 11; db++)
#pragma unroll
        for (int j = 0; j < 4; j++) oc[db][j] = 0.f;

    int la = (lane & ~3) | (tid >> 1);
    int lb = la + 2;
    bool odd = tid & 1;

    for (int kt = 0; kt < 16; kt++) {
        int k0 = kt * 64;
        __syncthreads();

        // ---- stage K from float4 row loads ----
        // word (ks,key,j,half) = (ks*256 + key*4 + j)*2 + half
        for (int i = t; i < 64*21; i += 256) {
            int key = i / 21, dg = i % 21;
            float4 v = *(const float4*)(kptr + (long)(k0 + key)*84 + dg*4);
            int ks = dg >> 1, half = dg & 1;
            int basew = (ks*256 + key*4)*2 + half;
            KpW[basew + 0] = v.x;
            KpW[basew + 2] = v.y;
            KpW[basew + 4] = v.z;
            KpW[basew + 6] = v.w;
        }
        // ---- stage V (hi/lo interleaved float4 per (d, ks, tid)) ----
        for (int i = t; i < 64*21; i += 256) {
            int key = i / 21, dg = i % 21;
            float4 v = *(const float4*)(vptr + (long)(k0 + key)*84 + dg*4);
            int ks = key >> 3, kk = key & 7;
            int tid4 = kk & 3, half = kk >> 2;
            int wb = ((dg*4)*36 + ks*4 + tid4)*4 + half;
            float vs[4] = {v.x, v.y, v.z, v.w};
#pragma unroll
            for (int j = 0; j < 4; j++) {
                float hv = tf32_hi(vs[j]);
                V4W[wb + j*144]     = hv;
                V4W[wb + j*144 + 2] = vs[j] - hv;
            }
        }
        __syncthreads();

        for (int nb = 0; nb < 8; nb++) {
            // ---- S block: 11 QK MMAs ----
            float c[4] = {0.f, 0.f, 0.f, 0.f};
            const float2* kb = Kp + (nb*8 + g)*4 + tid;
#pragma unroll
            for (int ks = 0; ks < 11; ks++) {
                float2 bf = kb[ks*256];
                MMA_TF32(c, qa[ks][0], qa[ks][1], qa[ks][2], qa[ks][3],
                         __float_as_uint(bf.x), __float_as_uint(bf.y));
            }
            // ---- bias + fixed-max softmax ----
            int n2 = k0 + nb*8 + 2*tid;
            int adj = n2 + 31*(n2 >> 5);
            float p0 = __expf(c[0] + TBs[base0 - adj]     - mr0);
            float p1 = __expf(c[1] + TBs[base0 - adj - 1] - mr0);
            float p2 = __expf(c[2] + TBs[base1 - adj]     - mr1);
            float p3 = __expf(c[3] + TBs[base1 - adj - 1] - mr1);
            lacc0 += p0 + p1;
            lacc1 += p2 + p3;
            // ---- C-frag -> A-frag via quad shuffles; round P to tf32 ----
            float s0 = __shfl_sync(0xffffffffu, p0, la);
            float s1 = __shfl_sync(0xffffffffu, p1, la);
            float s2 = __shfl_sync(0xffffffffu, p2, la);
            float s3 = __shfl_sync(0xffffffffu, p3, la);
            float s4 = __shfl_sync(0xffffffffu, p0, lb);
            float s5 = __shfl_sync(0xffffffffu, p1, lb);
            float s6 = __shfl_sync(0xffffffffu, p2, lb);
            float s7 = __shfl_sync(0xffffffffu, p3, lb);
            unsigned ua0 = tf32_rnd(odd ? s1 : s0);
            unsigned ua1 = tf32_rnd(odd ? s3 : s2);
            unsigned ua2 = tf32_rnd(odd ? s5 : s4);
            unsigned ua3 = tf32_rnd(odd ? s7 : s6);
            // ---- PV: 11 d-blocks x 2 MMAs, one LDS.128 per db ----
            const float4* vb = V4 + nb*4 + tid;
#pragma unroll
            for (int db = 0; db < 11; db++) {
                float4 vv = vb[(db*8 + g)*36];
                MMA_TF32(oc[db], ua0, ua1, ua2, ua3,
                         __float_as_uint(vv.x), __float_as_uint(vv.y));
                MMA_TF32(oc[db], ua0, ua1, ua2, ua3,
                         __float_as_uint(vv.z), __float_as_uint(vv.w));
            }
        }
    }

    // ---- epilogue: quad-reduce l, normalize, scatter ----
    lacc0 += __shfl_xor_sync(0xffffffffu, lacc0, 1);
    lacc0 += __shfl_xor_sync(0xffffffffu, lacc0, 2);
    lacc1 += __shfl_xor_sync(0xffffffffu, lacc1, 1);
    lacc1 += __shfl_xor_sync(0xffffffffu, lacc1, 2);
    float inv0 = 1.0f / lacc0, inv1 = 1.0f / lacc1;

    long cb0 = ((long)(b*NN + r0)*MM)*CC + h*HD;
    long cb1 = ((long)(b*NN + r1)*MM)*CC + h*HD;
#pragma unroll
    for (int db = 0; db < 11; db++) {
#pragma unroll
        for (int e = 0; e < 2; e++) {
            int d84 = db*8 + 2*tid + e;
            if (d84 < 84) {
                int m = d84 >> 2, dd = d84 & 3;
                g_ctx[cb0 + m*CC + dd] = oc[db][e]   * inv0;
                g_ctx[cb1 + m*CC + dd] = oc[db][2+e] * inv1;
            }
        }
    }
}

// ---------------- output projection ----------------
__global__ void __launch_bounds__(256) proj_kernel(const float* __restrict__ W,
                                                   const float* __restrict__ bias,
                                                   float* __restrict__ out) {
    __shared__ float Ws[32*32];
    __shared__ float xs[64][32];
    int t = threadIdx.x;
    for (int i = t; i < 1024; i += 256) Ws[i] = W[i];
    long rowbase = (long)blockIdx.x * 64;
    for (int i = t; i < 64*32; i += 256) {
        int r = i >> 5, c = i & 31;
        xs[r][c] = g_ctx[(rowbase + r)*32 + c];
    }
    __syncthreads();
    int ry = t >> 4, cx = t & 15;
    float acc[4][2] = {};
#pragma unroll
    for (int kk = 0; kk < 32; kk++) {
        float xv[4], wv[2];
#pragma unroll
        for (int u = 0; u < 4; u++) xv[u] = xs[ry*4+u][kk];
        wv[0] = Ws[kk*32 + cx*2];
        wv[1] = Ws[kk*32 + cx*2 + 1];
#pragma unroll
        for (int u = 0; u < 4; u++) { acc[u][0] += xv[u]*wv[0]; acc[u][1] += xv[u]*wv[1]; }
    }
#pragma unroll
    for (int u = 0; u < 4; u++)
#pragma unroll
        for (int v = 0; v < 2; v++)
            out[(rowbase + ry*4 + u)*32 + cx*2 + v] = acc[u][v] + bias[cx*2 + v];
}

// ---------------- launch ----------------
extern "C" void kernel_launch(void* const* d_in, const int* in_sizes, int n_in,
                              void* d_out, int out_size) {
    (void)in_sizes; (void)n_in; (void)out_size;
    const float* x     = (const float*)d_in[0];
    const float* Wqkv  = (const float*)d_in[1];
    const float* bqkv  = (const float*)d_in[2];
    const float* Wproj = (const float*)d_in[3];
    const float* bproj = (const float*)d_in[4];
    const float* Wsq   = (const float*)d_in[5];
    const float* bsq   = (const float*)d_in[6];
    const float* Wdw   = (const float*)d_in[7];
    const float* bdw   = (const float*)d_in[8];
    float* out = (float*)d_out;

    cudaFuncSetAttribute(flash_mma, cudaFuncAttributeMaxDynamicSharedMemorySize, SMEM_BYTES);
    cudaFuncSetAttribute(qkv2_kernel, cudaFuncAttributeMaxDynamicSharedMemorySize,
                         QKV_SMEMF * (int)sizeof(float));

    qkv2_kernel  <<<1024, 256, QKV_SMEMF*sizeof(float)>>>(x, Wqkv, bqkv, Wsq, bsq);
    pool_kernel  <<<BB*NHH, 256>>>();
    conv_kernel  <<<NHH, 1024>>>(Wdw, bdw);
    table_kernel <<<dim3(63, NHH), 512>>>();
    rowmax_kernel<<<NHH, 256>>>();
    flash_mma    <<<dim3(NN/128, BB*NHH), 256, SMEM_BYTES>>>();
    proj_kernel  <<<NROWS/64, 256>>>(Wproj, bproj, out);
}

// round 16
// speedup vs baseline: 2.2102x; 2.2102x over previous
#include <cuda_runtime.h>
#include <cstdint>

#define BB   4
#define NHH  8
#define NN   1024
#define MM   21
#define CC   32
#define HD   4
#define DD   84
#define NROWS (BB*NN*MM)

// ---------------- device scratch ----------------
__device__ float g_q[BB*NHH*NN*DD];
__device__ float g_k[BB*NHH*NN*DD];
__device__ float g_v[BB*NHH*NN*DD];      // row-major (bh, n, d84)
__device__ float g_x2[BB*NHH*NN];
__device__ float g_pool[BB*NHH];
__device__ float g_xw[NHH*NN];
__device__ float g_xp[NHH*NN];
__device__ float g_tb[NHH*63*63];
__device__ float g_rowmax[NHH*NN];
__device__ float g_ctx[NROWS*CC];

__device__ __forceinline__ unsigned tf32_rnd(float f) {
    return (__float_as_uint(f) + 0x1000u) & 0xFFFFE000u;
}

#define MMA_TF32(C, A0, A1, A2, A3, B0, B1) \
    asm volatile( \
        "mma.sync.aligned.m16n8k8.row.col.f32.tf32.tf32.f32 " \
        "{%0,%1,%2,%3}, {%4,%5,%6,%7}, {%8,%9}, {%0,%1,%2,%3};\n" \
        : "+f"((C)[0]), "+f"((C)[1]), "+f"((C)[2]), "+f"((C)[3]) \
        : "r"(A0), "r"(A1), "r"(A2), "r"(A3), "r"(B0), "r"(B1))

// ---------------- kernel A: qkv projection (coalesced writes) + fused x2 ----
#define QKV_OUT 0
#define QKV_XS  8400
#define QKV_WS  (QKV_XS + 84*33)
#define QKV_WSQ (QKV_WS + 3072)
#define QKV_SMEMF (QKV_WSQ + 84)

__global__ void __launch_bounds__(256) qkv2_kernel(const float* __restrict__ x,
                                                   const float* __restrict__ Wq,
                                                   const float* __restrict__ bq,
                                                   const float* __restrict__ Wsq,
                                                   const float* __restrict__ bsq) {
    extern __shared__ float sm[];
    float* out = sm + QKV_OUT;
    float* xs  = sm + QKV_XS;
    float* Ws  = sm + QKV_WS;
    float* wsq = sm + QKV_WSQ;
    int t = threadIdx.x;
    int blk = blockIdx.x;                       // 0..1023, 4 groups each
    long xbase = (long)blk * 84 * 32;

    for (int i = t; i < 84*32; i += 256) xs[(i >> 5)*33 + (i & 31)] = x[xbase + i];
    for (int i = t; i < 3072; i += 256) Ws[i] = Wq[i];
    if (t < 84) wsq[t] = Wsq[t];
    __syncthreads();

    if (t < 252) {
        int ry = t % 84, cg = t / 84;           // cg = which (0:q,1:k,2:v)
        float acc[32];
#pragma unroll
        for (int j = 0; j < 32; j++) acc[j] = bq[cg*32 + j];
        for (int kk = 0; kk < 32; kk++) {
            float xv = xs[ry*33 + kk];
#pragma unroll
            for (int j = 0; j < 32; j++) acc[j] += xv * Ws[kk*96 + cg*32 + j];
        }
#pragma unroll
        for (int j = 0; j < 32; j++) out[ry*100 + cg*32 + j] = acc[j];
    }

    // fused x2: one value per (group, head)
    if (t < 32) {
        int g = t >> 3, h = t & 7;
        float acc = bsq[0];
        for (int m = 0; m < 21; m++)
#pragma unroll
            for (int d = 0; d < 4; d++)
                acc += xs[(g*21 + m)*33 + h*4 + d] * wsq[m*4 + d];
        int b_ = blk*4 + g;
        g_x2[((b_ >> 10)*8 + h)*1024 + (b_ & 1023)] = acc;
    }
    __syncthreads();

    // coalesced write-out: 96 rows (4 groups x 8 heads x 3 tensors) of 84 floats
    int w = t >> 5, lane = t & 31;
#pragma unroll
    for (int it = 0; it < 12; it++) {
        int tk = w*12 + it;
        int g = tk / 24, rem = tk % 24, which = rem >> 3, h = rem & 7;
        int b_ = blk*4 + g;
        int bh = (b_ >> 10)*8 + h, n = b_ & 1023;
        float* dst = (which == 0 ? g_q : which == 1 ? g_k : g_v)
                     + ((long)bh*1024 + n)*84;
        for (int d84 = lane; d84 < 84; d84 += 32) {
            float s = out[(g*21 + (d84 >> 2))*100 + which*32 + h*4 + (d84 & 3)];
            dst[d84] = (which == 0) ? s * 0.03125f : s;
        }
    }
}

// ---------------- LSPE small kernels ----------------
__global__ void pool_kernel() {
    int bh = blockIdx.x, t = threadIdx.x;
    const float* p = g_x2 + bh*NN;
    float s = 0.f, mx = -1e30f;
    for (int i = t; i < NN; i += 256) { float v = p[i]; s += v; mx = fmaxf(mx, v); }
    __shared__ float ss[256], sm_[256];
    ss[t] = s; sm_[t] = mx;
    __syncthreads();
    for (int o = 128; o > 0; o >>= 1) {
        if (t < o) { ss[t] += ss[t+o]; sm_[t] = fmaxf(sm_[t], sm_[t+o]); }
        __syncthreads();
    }
    if (t == 0) g_pool[bh] = ss[0]*(1.f/1024.f) + sm_[0];
}

// conv: one block per input channel (group); 4 batch planes staged with zero halo
__global__ void __launch_bounds__(1024) conv_kernel(const float* __restrict__ Wdw,
                                                    const float* __restrict__ bdw) {
    int ic = blockIdx.x, t = threadIdx.x;
    __shared__ float sp[4*34*34];
    for (int i = t; i < 4*34*34; i += 1024) sp[i] = 0.f;
    __syncthreads();
    for (int i = t; i < 4096; i += 1024) {
        int b = i >> 10, pos = i & 1023;
        int y = pos >> 5, x = pos & 31;
        sp[b*1156 + (y+1)*34 + (x+1)] = g_x2[(b*NHH + ic)*NN + pos];
    }
    int o0 = 2*ic, o1 = 2*ic + 1;
    float w0[9], w1[9];
#pragma unroll
    for (int j = 0; j < 9; j++) { w0[j] = Wdw[o0*9 + j]; w1[j] = Wdw[o1*9 + j]; }
    float bd0 = bdw[o0], bd1 = bdw[o1];
    __syncthreads();

    int y = t >> 5, x = t & 31;
    float acc0 = 0.f, acc1 = 0.f;
#pragma unroll
    for (int b = 0; b < 4; b++) {
        const float* base = sp + b*1156 + y*34 + x;
        float pm0 = g_pool[b*NHH + (o0 & 7)];
        float pm1 = g_pool[b*NHH + (o1 & 7)];
        float c0 = bd0 + pm0, c1 = bd1 + pm1;
#pragma unroll
        for (int ky = 0; ky < 3; ky++)
#pragma unroll
            for (int kx = 0; kx < 3; kx++) {
                float s = base[ky*34 + kx];
                c0 += s * w0[ky*3 + kx];
                c1 += s * w1[ky*3 + kx];
            }
        acc0 += c0; acc1 += c1;
    }
    acc0 *= 0.25f; acc1 *= 0.25f;
    if (o0 < 8) { g_xw[o0*NN + t] = acc0; g_xw[o1*NN + t] = acc1; }
    else        { g_xp[(o0-8)*NN + t] = acc0; g_xp[(o1-8)*NN + t] = acc1; }
}

// table: grid (63, 8), 512 threads; 8 threads per output, padded pitch 33
__global__ void __launch_bounds__(512) table_kernel() {
    int p = blockIdx.x, h = blockIdx.y, t = threadIdx.x;
    __shared__ float xw[32*33], xp[32*33];
    for (int i = t; i < 1024; i += 512) {
        int r = i >> 5, c = i & 31;
        xw[r*33 + c] = g_xw[h*NN + i];
        xp[r*33 + c] = g_xp[h*NN + i];
    }
    __syncthreads();
    int q = t >> 3, part = t & 7;            // q 0..63 (63 unused)
    int alo = max(0, p-31), ahi = min(31, p);
    int blo = max(0, q-31), bhi = min(31, q);
    float acc0 = 0.f, acc1 = 0.f;
    for (int a = alo + part; a <= ahi; a += 8) {
        const float* xwr = xw + a*33;
        const float* xpr = xp + (p-a)*33;
        for (int b2 = blo; b2 + 1 <= bhi; b2 += 2) {
            acc0 += xwr[b2]     * xpr[q - b2];
            acc1 += xwr[b2 + 1] * xpr[q - b2 - 1];
        }
        if (((bhi - blo) & 1) == 0) acc0 += xwr[bhi] * xpr[q - bhi];
    }
    float acc = acc0 + acc1;
    acc += __shfl_xor_sync(0xffffffffu, acc, 1);
    acc += __shfl_xor_sync(0xffffffffu, acc, 2);
    acc += __shfl_xor_sync(0xffffffffu, acc, 4);
    if (part == 0 && q < 63) g_tb[h*3969 + p*63 + q] = acc;
}

// rowmax: separable 32x32 window max (col-max pass, then row-max pass)
__global__ void __launch_bounds__(256) rowmax_kernel() {
    int h = blockIdx.x, t = threadIdx.x;
    __shared__ float tb[3969];
    __shared__ float cm[32*63];
    for (int i = t; i < 3969; i += 256) tb[i] = g_tb[h*3969 + i];
    __syncthreads();
    for (int i = t; i < 32*63; i += 256) {
        int i1 = i / 63, j = i % 63;
        float m = tb[i1*63 + j];
#pragma unroll 4
        for (int a = 1; a < 32; a++) m = fmaxf(m, tb[(i1+a)*63 + j]);
        cm[i] = m;
    }
    __syncthreads();
    for (int n1 = t; n1 < 1024; n1 += 256) {
        int i1 = n1 >> 5, j1 = n1 & 31;
        float m = cm[i1*63 + j1];
#pragma unroll 4
        for (int b = 1; b < 32; b++) m = fmaxf(m, cm[i1*63 + j1 + b]);
        g_rowmax[h*NN + n1] = m;
    }
}

// ---------------- HMMA tf32 flash attention (R12 layout, single rounded-V PV) --
// SMEM: Kp 11*64*4 float2 = 22528 | Vp 88*36 float2 = 25344 | TBs 2205 f = 8820
#define KP_OFF 0
#define VP_OFF 22528
#define TB_OFF 47872
#define SMEM_BYTES 56704

__global__ void __launch_bounds__(256, 2) flash_mma() {
    extern __shared__ char smem[];
    float2* Kp  = (float2*)(smem + KP_OFF);
    float*  VpW = (float*)(smem + VP_OFF);
    float2* Vp2 = (float2*)(smem + VP_OFF);
    float*  TBs = (float*)(smem + TB_OFF);

    int t = threadIdx.x;
    int w = t >> 5, lane = t & 31;
    int g = lane >> 2, tid = lane & 3;
    int qt = blockIdx.x, bh = blockIdx.y;
    int h = bh & 7, b = bh >> 3;
    int q0 = qt * 128;

    const float* qptr = g_q + (long)bh*NN*DD;
    const float* kptr = g_k + (long)bh*NN*DD;
    const float* vptr = g_v + (long)bh*NN*DD;

    // bias table slice rows [qt*4 .. qt*4+34]
    int i1base = qt * 4;
    for (int i = t; i < 2205; i += 256) TBs[i] = g_tb[h*3969 + i1base*63 + i];
    // zero padded V rows 84..87 (never written by staging)
    for (int i = t; i < 4*36; i += 256) {
        int r = 84 + (i / 36), c = i % 36;
        Vp2[r*36 + c] = make_float2(0.f, 0.f);
    }

    // Q fragments: rows r0 = q0+w*16+g, r1 = r0+8; 11 ksteps
    unsigned qa[11][4];
    int r0 = q0 + w*16 + g, r1 = r0 + 8;
#pragma unroll
    for (int ks = 0; ks < 11; ks++) {
        int d0 = ks*8 + tid;
        qa[ks][0] = __float_as_uint(qptr[(long)r0*84 + d0]);
        qa[ks][1] = __float_as_uint(qptr[(long)r1*84 + d0]);
        qa[ks][2] = (d0+4 < 84) ? __float_as_uint(qptr[(long)r0*84 + d0+4]) : 0u;
        qa[ks][3] = (d0+4 < 84) ? __float_as_uint(qptr[(long)r1*84 + d0+4]) : 0u;
    }

    float mr0 = g_rowmax[h*NN + r0] + 1.0f;
    float mr1 = g_rowmax[h*NN + r1] + 1.0f;
    int base0 = ((r0 >> 5) - i1base + 31)*63 + (r0 & 31) + 31;
    int base1 = ((r1 >> 5) - i1base + 31)*63 + (r1 & 31) + 31;
    float lacc0 = 0.f, lacc1 = 0.f;

    float oc[11][4];
#pragma unroll
    for (int db = 0; db < 11; db++)
#pragma unroll
        for (int j = 0; j < 4; j++) oc[db][j] = 0.f;

    int la = (lane & ~3) | (tid >> 1);
    int lb = la + 2;
    bool odd = tid & 1;

    for (int kt = 0; kt < 16; kt++) {
        int k0 = kt * 64;
        __syncthreads();

        // ---- stage K (R12 layout): Kp[ks*256 + key*4 + tid] ----
        for (int i = t; i < 11*64*4; i += 256) {
            int tid4 = i & 3, key = (i >> 2) & 63, ks = i >> 8;
            int d0 = ks*8 + tid4;
            const float* kr = kptr + (long)(k0 + key)*84;
            float2 v;
            v.x = kr[d0];
            v.y = (d0+4 < 84) ? kr[d0+4] : 0.f;
            Kp[i] = v;
        }
        // ---- stage V (single, tf32-rounded; R12 word layout) ----
        for (int i = t; i < 64*21; i += 256) {
            int key = i / 21, dg = i % 21;
            float4 v = *(const float4*)(vptr + (long)(k0 + key)*84 + dg*4);
            int ks = key >> 3, kk = key & 7;
            int tid4 = kk & 3, half = kk >> 2;
            int wb = (dg*4)*72 + ks*8 + tid4*2 + half;
            float vs[4] = {v.x, v.y, v.z, v.w};
#pragma unroll
            for (int j = 0; j < 4; j++)
                VpW[wb + j*72] = __uint_as_float(tf32_rnd(vs[j]));
        }
        __syncthreads();

        for (int nb = 0; nb < 8; nb++) {
            // ---- S block: 11 QK MMAs ----
            float c[4] = {0.f, 0.f, 0.f, 0.f};
            const float2* kb = Kp + (nb*8 + g)*4 + tid;
#pragma unroll
            for (int ks = 0; ks < 11; ks++) {
                float2 bf = kb[ks*256];
                MMA_TF32(c, qa[ks][0], qa[ks][1], qa[ks][2], qa[ks][3],
                         __float_as_uint(bf.x), __float_as_uint(bf.y));
            }
            // ---- bias + fixed-max softmax ----
            int n2 = k0 + nb*8 + 2*tid;
            int adj = n2 + 31*(n2 >> 5);
            float p0 = __expf(c[0] + TBs[base0 - adj]     - mr0);
            float p1 = __expf(c[1] + TBs[base0 - adj - 1] - mr0);
            float p2 = __expf(c[2] + TBs[base1 - adj]     - mr1);
            float p3 = __expf(c[3] + TBs[base1 - adj - 1] - mr1);
            lacc0 += p0 + p1;
            lacc1 += p2 + p3;
            // ---- C-frag -> A-frag via quad shuffles; round P to tf32 ----
            float s0 = __shfl_sync(0xffffffffu, p0, la);
            float s1 = __shfl_sync(0xffffffffu, p1, la);
            float s2 = __shfl_sync(0xffffffffu, p2, la);
            float s3 = __shfl_sync(0xffffffffu, p3, la);
            float s4 = __shfl_sync(0xffffffffu, p0, lb);
            float s5 = __shfl_sync(0xffffffffu, p1, lb);
            float s6 = __shfl_sync(0xffffffffu, p2, lb);
            float s7 = __shfl_sync(0xffffffffu, p3, lb);
            unsigned ua0 = tf32_rnd(odd ? s1 : s0);   // (row g,   col tid)
            unsigned ua1 = tf32_rnd(odd ? s3 : s2);   // (row g+8, col tid)
            unsigned ua2 = tf32_rnd(odd ? s5 : s4);   // (row g,   col tid+4)
            unsigned ua3 = tf32_rnd(odd ? s7 : s6);   // (row g+8, col tid+4)
            // ---- PV: 11 d-blocks x 1 MMA (V pre-rounded to tf32) ----
            const float2* vb = Vp2 + nb*4 + tid;
#pragma unroll
            for (int db = 0; db < 11; db++) {
                float2 vv = vb[(db*8 + g)*36];
                MMA_TF32(oc[db], ua0, ua1, ua2, ua3,
                         __float_as_uint(vv.x), __float_as_uint(vv.y));
            }
        }
    }

    // ---- epilogue: quad-reduce l, normalize, scatter ----
    lacc0 += __shfl_xor_sync(0xffffffffu, lacc0, 1);
    lacc0 += __shfl_xor_sync(0xffffffffu, lacc0, 2);
    lacc1 += __shfl_xor_sync(0xffffffffu, lacc1, 1);
    lacc1 += __shfl_xor_sync(0xffffffffu, lacc1, 2);
    float inv0 = 1.0f / lacc0, inv1 = 1.0f / lacc1;

    long cb0 = ((long)(b*NN + r0)*MM)*CC + h*HD;
    long cb1 = ((long)(b*NN + r1)*MM)*CC + h*HD;
#pragma unroll
    for (int db = 0; db < 11; db++) {
#pragma unroll
        for (int e = 0; e < 2; e++) {
            int d84 = db*8 + 2*tid + e;
            if (d84 < 84) {
                int m = d84 >> 2, dd = d84 & 3;
                g_ctx[cb0 + m*CC + dd] = oc[db][e]   * inv0;
                g_ctx[cb1 + m*CC + dd] = oc[db][2+e] * inv1;
            }
        }
    }
}

// ---------------- output projection ----------------
__global__ void __launch_bounds__(256) proj_kernel(const float* __restrict__ W,
                                                   const float* __restrict__ bias,
                                                   float* __restrict__ out) {
    __shared__ float Ws[32*32];
    __shared__ float xs[64][32];
    int t = threadIdx.x;
    for (int i = t; i < 1024; i += 256) Ws[i] = W[i];
    long rowbase = (long)blockIdx.x * 64;
    for (int i = t; i < 64*32; i += 256) {
        int r = i >> 5, c = i & 31;
        xs[r][c] = g_ctx[(rowbase + r)*32 + c];
    }
    __syncthreads();
    int ry = t >> 4, cx = t & 15;
    float acc[4][2] = {};
#pragma unroll
    for (int kk = 0; kk < 32; kk++) {
        float xv[4], wv[2];
#pragma unroll
        for (int u = 0; u < 4; u++) xv[u] = xs[ry*4+u][kk];
        wv[0] = Ws[kk*32 + cx*2];
        wv[1] = Ws[kk*32 + cx*2 + 1];
#pragma unroll
        for (int u = 0; u < 4; u++) { acc[u][0] += xv[u]*wv[0]; acc[u][1] += xv[u]*wv[1]; }
    }
#pragma unroll
    for (int u = 0; u < 4; u++)
#pragma unroll
        for (int v = 0; v < 2; v++)
            out[(rowbase + ry*4 + u)*32 + cx*2 + v] = acc[u][v] + bias[cx*2 + v];
}

// ---------------- launch ----------------
extern "C" void kernel_launch(void* const* d_in, const int* in_sizes, int n_in,
                              void* d_out, int out_size) {
    (void)in_sizes; (void)n_in; (void)out_size;
    const float* x     = (const float*)d_in[0];
    const float* Wqkv  = (const float*)d_in[1];
    const float* bqkv  = (const float*)d_in[2];
    const float* Wproj = (const float*)d_in[3];
    const float* bproj = (const float*)d_in[4];
    const float* Wsq   = (const float*)d_in[5];
    const float* bsq   = (const float*)d_in[6];
    const float* Wdw   = (const float*)d_in[7];
    const float* bdw   = (const float*)d_in[8];
    float* out = (float*)d_out;

    cudaFuncSetAttribute(flash_mma, cudaFuncAttributeMaxDynamicSharedMemorySize, SMEM_BYTES);
    cudaFuncSetAttribute(qkv2_kernel, cudaFuncAttributeMaxDynamicSharedMemorySize,
                         QKV_SMEMF * (int)sizeof(float));

    qkv2_kernel  <<<1024, 256, QKV_SMEMF*sizeof(float)>>>(x, Wqkv, bqkv, Wsq, bsq);
    pool_kernel  <<<BB*NHH, 256>>>();
    conv_kernel  <<<NHH, 1024>>>(Wdw, bdw);
    table_kernel <<<dim3(63, NHH), 512>>>();
    rowmax_kernel<<<NHH, 256>>>();
    flash_mma    <<<dim3(NN/128, BB*NHH), 256, SMEM_BYTES>>>();
    proj_kernel  <<<NROWS/64, 256>>>(Wproj, bproj, out);
}

// round 17
// speedup vs baseline: 2.2658x; 1.0252x over previous
#include <cuda_runtime.h>
#include <cuda_bf16.h>
#include <cstdint>

#define BB   4
#define NHH  8
#define NN   1024
#define MM   21
#define CC   32
#define HD   4
#define DD   84
#define NROWS (BB*NN*MM)

// ---------------- device scratch ----------------
__device__ float g_q[BB*NHH*NN*DD];
__device__ float g_k[BB*NHH*NN*DD];
__device__ float g_v[BB*NHH*NN*DD];      // row-major (bh, n, d84)
__device__ float g_x2[BB*NHH*NN];
__device__ float g_pool[BB*NHH];
__device__ float g_xw[NHH*NN];
__device__ float g_xp[NHH*NN];
__device__ float g_tb[NHH*63*63];
__device__ float g_rowmax[NHH*NN];
__device__ float g_ctx[NROWS*CC];

__device__ __forceinline__ unsigned tf32_rnd(float f) {
    return (__float_as_uint(f) + 0x1000u) & 0xFFFFE000u;
}
__device__ __forceinline__ unsigned bf16pack(float a, float b) {
    __nv_bfloat162 v = __floats2bfloat162_rn(a, b);
    return *(unsigned*)&v;
}

#define MMA_TF32(C, A0, A1, A2, A3, B0, B1) \
    asm volatile( \
        "mma.sync.aligned.m16n8k8.row.col.f32.tf32.tf32.f32 " \
        "{%0,%1,%2,%3}, {%4,%5,%6,%7}, {%8,%9}, {%0,%1,%2,%3};\n" \
        : "+f"((C)[0]), "+f"((C)[1]), "+f"((C)[2]), "+f"((C)[3]) \
        : "r"(A0), "r"(A1), "r"(A2), "r"(A3), "r"(B0), "r"(B1))

#define MMA_BF16(C, A0, A1, A2, A3, B0, B1) \
    asm volatile( \
        "mma.sync.aligned.m16n8k16.row.col.f32.bf16.bf16.f32 " \
        "{%0,%1,%2,%3}, {%4,%5,%6,%7}, {%8,%9}, {%0,%1,%2,%3};\n" \
        : "+f"((C)[0]), "+f"((C)[1]), "+f"((C)[2]), "+f"((C)[3]) \
        : "r"(A0), "r"(A1), "r"(A2), "r"(A3), "r"(B0), "r"(B1))

// ---------------- kernel A: qkv projection (coalesced writes) + fused x2 ----
#define QKV_OUT 0
#define QKV_XS  8400
#define QKV_WS  (QKV_XS + 84*33)
#define QKV_WSQ (QKV_WS + 3072)
#define QKV_SMEMF (QKV_WSQ + 84)

__global__ void __launch_bounds__(256) qkv2_kernel(const float* __restrict__ x,
                                                   const float* __restrict__ Wq,
                                                   const float* __restrict__ bq,
                                                   const float* __restrict__ Wsq,
                                                   const float* __restrict__ bsq) {
    extern __shared__ float sm[];
    float* out = sm + QKV_OUT;
    float* xs  = sm + QKV_XS;
    float* Ws  = sm + QKV_WS;
    float* wsq = sm + QKV_WSQ;
    int t = threadIdx.x;
    int blk = blockIdx.x;                       // 0..1023, 4 groups each
    long xbase = (long)blk * 84 * 32;

    for (int i = t; i < 84*32; i += 256) xs[(i >> 5)*33 + (i & 31)] = x[xbase + i];
    for (int i = t; i < 3072; i += 256) Ws[i] = Wq[i];
    if (t < 84) wsq[t] = Wsq[t];
    __syncthreads();

    if (t < 252) {
        int ry = t % 84, cg = t / 84;           // cg = which (0:q,1:k,2:v)
        float acc[32];
#pragma unroll
        for (int j = 0; j < 32; j++) acc[j] = bq[cg*32 + j];
        for (int kk = 0; kk < 32; kk++) {
            float xv = xs[ry*33 + kk];
#pragma unroll
            for (int j = 0; j < 32; j++) acc[j] += xv * Ws[kk*96 + cg*32 + j];
        }
#pragma unroll
        for (int j = 0; j < 32; j++) out[ry*100 + cg*32 + j] = acc[j];
    }

    // fused x2: one value per (group, head)
    if (t < 32) {
        int g = t >> 3, h = t & 7;
        float acc = bsq[0];
        for (int m = 0; m < 21; m++)
#pragma unroll
            for (int d = 0; d < 4; d++)
                acc += xs[(g*21 + m)*33 + h*4 + d] * wsq[m*4 + d];
        int b_ = blk*4 + g;
        g_x2[((b_ >> 10)*8 + h)*1024 + (b_ & 1023)] = acc;
    }
    __syncthreads();

    // coalesced write-out: 96 rows (4 groups x 8 heads x 3 tensors) of 84 floats
    int w = t >> 5, lane = t & 31;
#pragma unroll
    for (int it = 0; it < 12; it++) {
        int tk = w*12 + it;
        int g = tk / 24, rem = tk % 24, which = rem >> 3, h = rem & 7;
        int b_ = blk*4 + g;
        int bh = (b_ >> 10)*8 + h, n = b_ & 1023;
        float* dst = (which == 0 ? g_q : which == 1 ? g_k : g_v)
                     + ((long)bh*1024 + n)*84;
        for (int d84 = lane; d84 < 84; d84 += 32) {
            float s = out[(g*21 + (d84 >> 2))*100 + which*32 + h*4 + (d84 & 3)];
            dst[d84] = (which == 0) ? s * 0.03125f : s;
        }
    }
}

// ---------------- LSPE small kernels ----------------
__global__ void pool_kernel() {
    int bh = blockIdx.x, t = threadIdx.x;
    const float* p = g_x2 + bh*NN;
    float s = 0.f, mx = -1e30f;
    for (int i = t; i < NN; i += 256) { float v = p[i]; s += v; mx = fmaxf(mx, v); }
    __shared__ float ss[256], sm_[256];
    ss[t] = s; sm_[t] = mx;
    __syncthreads();
    for (int o = 128; o > 0; o >>= 1) {
        if (t < o) { ss[t] += ss[t+o]; sm_[t] = fmaxf(sm_[t], sm_[t+o]); }
        __syncthreads();
    }
    if (t == 0) g_pool[bh] = ss[0]*(1.f/1024.f) + sm_[0];
}

// conv: one block per input channel (group); 4 batch planes staged with zero halo
__global__ void __launch_bounds__(1024) conv_kernel(const float* __restrict__ Wdw,
                                                    const float* __restrict__ bdw) {
    int ic = blockIdx.x, t = threadIdx.x;
    __shared__ float sp[4*34*34];
    for (int i = t; i < 4*34*34; i += 1024) sp[i] = 0.f;
    __syncthreads();
    for (int i = t; i < 4096; i += 1024) {
        int b = i >> 10, pos = i & 1023;
        int y = pos >> 5, x = pos & 31;
        sp[b*1156 + (y+1)*34 + (x+1)] = g_x2[(b*NHH + ic)*NN + pos];
    }
    int o0 = 2*ic, o1 = 2*ic + 1;
    float w0[9], w1[9];
#pragma unroll
    for (int j = 0; j < 9; j++) { w0[j] = Wdw[o0*9 + j]; w1[j] = Wdw[o1*9 + j]; }
    float bd0 = bdw[o0], bd1 = bdw[o1];
    __syncthreads();

    int y = t >> 5, x = t & 31;
    float acc0 = 0.f, acc1 = 0.f;
#pragma unroll
    for (int b = 0; b < 4; b++) {
        const float* base = sp + b*1156 + y*34 + x;
        float pm0 = g_pool[b*NHH + (o0 & 7)];
        float pm1 = g_pool[b*NHH + (o1 & 7)];
        float c0 = bd0 + pm0, c1 = bd1 + pm1;
#pragma unroll
        for (int ky = 0; ky < 3; ky++)
#pragma unroll
            for (int kx = 0; kx < 3; kx++) {
                float s = base[ky*34 + kx];
                c0 += s * w0[ky*3 + kx];
                c1 += s * w1[ky*3 + kx];
            }
        acc0 += c0; acc1 += c1;
    }
    acc0 *= 0.25f; acc1 *= 0.25f;
    if (o0 < 8) { g_xw[o0*NN + t] = acc0; g_xw[o1*NN + t] = acc1; }
    else        { g_xp[(o0-8)*NN + t] = acc0; g_xp[(o1-8)*NN + t] = acc1; }
}

// table: grid (63, 8), 512 threads; 8 threads per output, padded pitch 33
__global__ void __launch_bounds__(512) table_kernel() {
    int p = blockIdx.x, h = blockIdx.y, t = threadIdx.x;
    __shared__ float xw[32*33], xp[32*33];
    for (int i = t; i < 1024; i += 512) {
        int r = i >> 5, c = i & 31;
        xw[r*33 + c] = g_xw[h*NN + i];
        xp[r*33 + c] = g_xp[h*NN + i];
    }
    __syncthreads();
    int q = t >> 3, part = t & 7;            // q 0..63 (63 unused)
    int alo = max(0, p-31), ahi = min(31, p);
    int blo = max(0, q-31), bhi = min(31, q);
    float acc0 = 0.f, acc1 = 0.f;
    for (int a = alo + part; a <= ahi; a += 8) {
        const float* xwr = xw + a*33;
        const float* xpr = xp + (p-a)*33;
        for (int b2 = blo; b2 + 1 <= bhi; b2 += 2) {
            acc0 += xwr[b2]     * xpr[q - b2];
            acc1 += xwr[b2 + 1] * xpr[q - b2 - 1];
        }
        if (((bhi - blo) & 1) == 0) acc0 += xwr[bhi] * xpr[q - bhi];
    }
    float acc = acc0 + acc1;
    acc += __shfl_xor_sync(0xffffffffu, acc, 1);
    acc += __shfl_xor_sync(0xffffffffu, acc, 2);
    acc += __shfl_xor_sync(0xffffffffu, acc, 4);
    if (part == 0 && q < 63) g_tb[h*3969 + p*63 + q] = acc;
}

// rowmax: separable 32x32 window max (col-max pass, then row-max pass)
__global__ void __launch_bounds__(256) rowmax_kernel() {
    int h = blockIdx.x, t = threadIdx.x;
    __shared__ float tb[3969];
    __shared__ float cm[32*63];
    for (int i = t; i < 3969; i += 256) tb[i] = g_tb[h*3969 + i];
    __syncthreads();
    for (int i = t; i < 32*63; i += 256) {
        int i1 = i / 63, j = i % 63;
        float m = tb[i1*63 + j];
#pragma unroll 4
        for (int a = 1; a < 32; a++) m = fmaxf(m, tb[(i1+a)*63 + j]);
        cm[i] = m;
    }
    __syncthreads();
    for (int n1 = t; n1 < 1024; n1 += 256) {
        int i1 = n1 >> 5, j1 = n1 & 31;
        float m = cm[i1*63 + j1];
#pragma unroll 4
        for (int b = 1; b < 32; b++) m = fmaxf(m, cm[i1*63 + j1 + b]);
        g_rowmax[h*NN + n1] = m;
    }
}

// ---------------- flash attention: bf16 QK (m16n8k16) + tf32 rounded-V PV ----
// SMEM: Kb 6*64*4 uint2 = 12288 | Vp 88*36 float2 = 25344 | TBs 2205 f = 8820
#define KB_OFF 0
#define VP_OFF 12288
#define TB_OFF 37632
#define SMEM_BYTES 46464

__global__ void __launch_bounds__(256, 2) flash_mma() {
    extern __shared__ char smem[];
    uint2*  Kb  = (uint2*)(smem + KB_OFF);
    float*  VpW = (float*)(smem + VP_OFF);
    float2* Vp2 = (float2*)(smem + VP_OFF);
    float*  TBs = (float*)(smem + TB_OFF);

    int t = threadIdx.x;
    int w = t >> 5, lane = t & 31;
    int g = lane >> 2, tid = lane & 3;
    int qt = blockIdx.x, bh = blockIdx.y;
    int h = bh & 7, b = bh >> 3;
    int q0 = qt * 128;

    const float* qptr = g_q + (long)bh*NN*DD;
    const float* kptr = g_k + (long)bh*NN*DD;
    const float* vptr = g_v + (long)bh*NN*DD;

    // bias table slice rows [qt*4 .. qt*4+34]
    int i1base = qt * 4;
    for (int i = t; i < 2205; i += 256) TBs[i] = g_tb[h*3969 + i1base*63 + i];
    // zero padded V rows 84..87 (never written by staging)
    for (int i = t; i < 4*36; i += 256) {
        int r = 84 + (i / 36), c = i % 36;
        Vp2[r*36 + c] = make_float2(0.f, 0.f);
    }

    // Q bf16 A-fragments: rows r0 = q0+w*16+g, r1 = r0+8; 6 k16-steps
    unsigned qa[6][4];
    int r0 = q0 + w*16 + g, r1 = r0 + 8;
    const float* q0p = qptr + (long)r0*84;
    const float* q1p = qptr + (long)r1*84;
#pragma unroll
    for (int ks = 0; ks < 6; ks++) {
        int d0 = ks*16 + 2*tid;
        float a00 = (d0   < 84) ? q0p[d0]   : 0.f;
        float a01 = (d0+1 < 84) ? q0p[d0+1] : 0.f;
        float a10 = (d0   < 84) ? q1p[d0]   : 0.f;
        float a11 = (d0+1 < 84) ? q1p[d0+1] : 0.f;
        float a02 = (d0+8 < 84) ? q0p[d0+8] : 0.f;
        float a03 = (d0+9 < 84) ? q0p[d0+9] : 0.f;
        float a12 = (d0+8 < 84) ? q1p[d0+8] : 0.f;
        float a13 = (d0+9 < 84) ? q1p[d0+9] : 0.f;
        qa[ks][0] = bf16pack(a00, a01);
        qa[ks][1] = bf16pack(a10, a11);
        qa[ks][2] = bf16pack(a02, a03);
        qa[ks][3] = bf16pack(a12, a13);
    }

    float mr0 = g_rowmax[h*NN + r0] + 1.0f;
    float mr1 = g_rowmax[h*NN + r1] + 1.0f;
    int base0 = ((r0 >> 5) - i1base + 31)*63 + (r0 & 31) + 31;
    int base1 = ((r1 >> 5) - i1base + 31)*63 + (r1 & 31) + 31;
    float lacc0 = 0.f, lacc1 = 0.f;

    float oc[11][4];
#pragma unroll
    for (int db = 0; db < 11; db++)
#pragma unroll
        for (int j = 0; j < 4; j++) oc[db][j] = 0.f;

    int la = (lane & ~3) | (tid >> 1);
    int lb = la + 2;
    bool odd = tid & 1;

    for (int kt = 0; kt < 16; kt++) {
        int k0 = kt * 64;
        __syncthreads();

        // ---- stage K as bf16 uint2: Kb[ks*256 + key*4 + tid] ----
        for (int i = t; i < 6*64*4; i += 256) {
            int tid4 = i & 3, key = (i >> 2) & 63, ks = i >> 8;
            int d0 = ks*16 + 2*tid4;
            const float* kr = kptr + (long)(k0 + key)*84;
            float x0 = (d0   < 84) ? kr[d0]   : 0.f;
            float x1 = (d0+1 < 84) ? kr[d0+1] : 0.f;
            float x2 = (d0+8 < 84) ? kr[d0+8] : 0.f;
            float x3 = (d0+9 < 84) ? kr[d0+9] : 0.f;
            uint2 u;
            u.x = bf16pack(x0, x1);
            u.y = bf16pack(x2, x3);
            Kb[i] = u;
        }
        // ---- stage V (single, tf32-rounded) ----
        for (int i = t; i < 64*21; i += 256) {
            int key = i / 21, dg = i % 21;
            float4 v = *(const float4*)(vptr + (long)(k0 + key)*84 + dg*4);
            int ks = key >> 3, kk = key & 7;
            int tid4 = kk & 3, half = kk >> 2;
            int wb = (dg*4)*72 + ks*8 + tid4*2 + half;
            float vs[4] = {v.x, v.y, v.z, v.w};
#pragma unroll
            for (int j = 0; j < 4; j++)
                VpW[wb + j*72] = __uint_as_float(tf32_rnd(vs[j]));
        }
        __syncthreads();

        for (int nb = 0; nb < 8; nb++) {
            // ---- S block: 6 bf16 k16 MMAs ----
            float c[4] = {0.f, 0.f, 0.f, 0.f};
            const uint2* kb = Kb + (nb*8 + g)*4 + tid;
#pragma unroll
            for (int ks = 0; ks < 6; ks++) {
                uint2 bf = kb[ks*256];
                MMA_BF16(c, qa[ks][0], qa[ks][1], qa[ks][2], qa[ks][3],
                         bf.x, bf.y);
            }
            // ---- bias + fixed-max softmax ----
            int n2 = k0 + nb*8 + 2*tid;
            int adj = n2 + 31*(n2 >> 5);
            float p0 = __expf(c[0] + TBs[base0 - adj]     - mr0);
            float p1 = __expf(c[1] + TBs[base0 - adj - 1] - mr0);
            float p2 = __expf(c[2] + TBs[base1 - adj]     - mr1);
            float p3 = __expf(c[3] + TBs[base1 - adj - 1] - mr1);
            lacc0 += p0 + p1;
            lacc1 += p2 + p3;
            // ---- C-frag -> A-frag via quad shuffles; round P to tf32 ----
            float s0 = __shfl_sync(0xffffffffu, p0, la);
            float s1 = __shfl_sync(0xffffffffu, p1, la);
            float s2 = __shfl_sync(0xffffffffu, p2, la);
            float s3 = __shfl_sync(0xffffffffu, p3, la);
            float s4 = __shfl_sync(0xffffffffu, p0, lb);
            float s5 = __shfl_sync(0xffffffffu, p1, lb);
            float s6 = __shfl_sync(0xffffffffu, p2, lb);
            float s7 = __shfl_sync(0xffffffffu, p3, lb);
            unsigned ua0 = tf32_rnd(odd ? s1 : s0);   // (row g,   col tid)
            unsigned ua1 = tf32_rnd(odd ? s3 : s2);   // (row g+8, col tid)
            unsigned ua2 = tf32_rnd(odd ? s5 : s4);   // (row g,   col tid+4)
            unsigned ua3 = tf32_rnd(odd ? s7 : s6);   // (row g+8, col tid+4)
            // ---- PV: 11 d-blocks x 1 tf32 MMA (V pre-rounded) ----
            const float2* vb = Vp2 + nb*4 + tid;
#pragma unroll
            for (int db = 0; db < 11; db++) {
                float2 vv = vb[(db*8 + g)*36];
                MMA_TF32(oc[db], ua0, ua1, ua2, ua3,
                         __float_as_uint(vv.x), __float_as_uint(vv.y));
            }
        }
    }

    // ---- epilogue: quad-reduce l, normalize, scatter ----
    lacc0 += __shfl_xor_sync(0xffffffffu, lacc0, 1);
    lacc0 += __shfl_xor_sync(0xffffffffu, lacc0, 2);
    lacc1 += __shfl_xor_sync(0xffffffffu, lacc1, 1);
    lacc1 += __shfl_xor_sync(0xffffffffu, lacc1, 2);
    float inv0 = 1.0f / lacc0, inv1 = 1.0f / lacc1;

    long cb0 = ((long)(b*NN + r0)*MM)*CC + h*HD;
    long cb1 = ((long)(b*NN + r1)*MM)*CC + h*HD;
#pragma unroll
    for (int db = 0; db < 11; db++) {
#pragma unroll
        for (int e = 0; e < 2; e++) {
            int d84 = db*8 + 2*tid + e;
            if (d84 < 84) {
                int m = d84 >> 2, dd = d84 & 3;
                g_ctx[cb0 + m*CC + dd] = oc[db][e]   * inv0;
                g_ctx[cb1 + m*CC + dd] = oc[db][2+e] * inv1;
            }
        }
    }
}

// ---------------- output projection ----------------
__global__ void __launch_bounds__(256) proj_kernel(const float* __restrict__ W,
                                                   const float* __restrict__ bias,
                                                   float* __restrict__ out) {
    __shared__ float Ws[32*32];
    __shared__ float xs[64][32];
    int t = threadIdx.x;
    for (int i = t; i < 1024; i += 256) Ws[i] = W[i];
    long rowbase = (long)blockIdx.x * 64;
    for (int i = t; i < 64*32; i += 256) {
        int r = i >> 5, c = i & 31;
        xs[r][c] = g_ctx[(rowbase + r)*32 + c];
    }
    __syncthreads();
    int ry = t >> 4, cx = t & 15;
    float acc[4][2] = {};
#pragma unroll
    for (int kk = 0; kk < 32; kk++) {
        float xv[4], wv[2];
#pragma unroll
        for (int u = 0; u < 4; u++) xv[u] = xs[ry*4+u][kk];
        wv[0] = Ws[kk*32 + cx*2];
        wv[1] = Ws[kk*32 + cx*2 + 1];
#pragma unroll
        for (int u = 0; u < 4; u++) { acc[u][0] += xv[u]*wv[0]; acc[u][1] += xv[u]*wv[1]; }
    }
#pragma unroll
    for (int u = 0; u < 4; u++)
#pragma unroll
        for (int v = 0; v < 2; v++)
            out[(rowbase + ry*4 + u)*32 + cx*2 + v] = acc[u][v] + bias[cx*2 + v];
}

// ---------------- launch ----------------
extern "C" void kernel_launch(void* const* d_in, const int* in_sizes, int n_in,
                              void* d_out, int out_size) {
    (void)in_sizes; (void)n_in; (void)out_size;
    const float* x     = (const float*)d_in[0];
    const float* Wqkv  = (const float*)d_in[1];
    const float* bqkv  = (const float*)d_in[2];
    const float* Wproj = (const float*)d_in[3];
    const float* bproj = (const float*)d_in[4];
    const float* Wsq   = (const float*)d_in[5];
    const float* bsq   = (const float*)d_in[6];
    const float* Wdw   = (const float*)d_in[7];
    const float* bdw   = (const float*)d_in[8];
    float* out = (float*)d_out;

    cudaFuncSetAttribute(flash_mma, cudaFuncAttributeMaxDynamicSharedMemorySize, SMEM_BYTES);
    cudaFuncSetAttribute(qkv2_kernel, cudaFuncAttributeMaxDynamicSharedMemorySize,
                         QKV_SMEMF * (int)sizeof(float));

    qkv2_kernel  <<<1024, 256, QKV_SMEMF*sizeof(float)>>>(x, Wqkv, bqkv, Wsq, bsq);
    pool_kernel  <<<BB*NHH, 256>>>();
    conv_kernel  <<<NHH, 1024>>>(Wdw, bdw);
    table_kernel <<<dim3(63, NHH), 512>>>();
    rowmax_kernel<<<NHH, 256>>>();
    flash_mma    <<<dim3(NN/128, BB*NHH), 256, SMEM_BYTES>>>();
    proj_kernel  <<<NROWS/64, 256>>>(Wproj, bproj, out);
}